// round 15
// baseline (speedup 1.0000x reference)
#include <cuda_runtime.h>
#include <cuda_bf16.h>
#include <cstdint>
#include <math.h>

// ---- problem constants ----
#define B_    4
#define NTOT  400
#define N1    256
#define N2    144
#define DIM   256
#define NH    8

// ---- scratch ----
__device__ float g_fqk[B_ * NTOT * 512];
__device__ float g_cqk[B_ * NTOT * 128];
__device__ float g_favg[B_ * NTOT * 256];                // window means of x
__device__ __nv_bfloat16 g_attnh[B_ * NH * NTOT * 256];  // attn bf16 hi (cols>=cnt stay 0)
__device__ __nv_bfloat16 g_attnl[B_ * NH * NTOT * 256];  // attn bf16 lo
__device__ __nv_bfloat16 g_x1h[16777216], g_x1l[16777216];
__device__ __nv_bfloat16 g_x2h[9437184],  g_x2l[9437184];
__device__ __nv_bfloat16 g_mixh[26214400];   // attn-mixed x, bf16 hi
__device__ __nv_bfloat16 g_mixl[26214400];   // bf16 lo residual
__device__ __nv_bfloat16 g_w2h[65536];       // W2 = vb_w @ v_w, bf16 hi
__device__ __nv_bfloat16 g_w2l[65536];       // bf16 lo

// ============================================================================
// helpers
// ============================================================================
__device__ __forceinline__ uint32_t smem_u32(const void* p) {
    uint32_t a;
    asm("{ .reg .u64 t; cvta.to.shared.u64 t, %1; cvt.u32.u64 %0, t; }" : "=r"(a) : "l"(p));
    return a;
}

#define LDSM_X4(r0, r1, r2, r3, addr) \
    asm volatile("ldmatrix.sync.aligned.m8n8.x4.shared.b16 {%0,%1,%2,%3}, [%4];" \
        : "=r"(r0), "=r"(r1), "=r"(r2), "=r"(r3) : "r"(addr))

#define LDSM_X4_T(r0, r1, r2, r3, addr) \
    asm volatile("ldmatrix.sync.aligned.m8n8.x4.trans.shared.b16 {%0,%1,%2,%3}, [%4];" \
        : "=r"(r0), "=r"(r1), "=r"(r2), "=r"(r3) : "r"(addr))

#define MMA16816(d, a0, a1, a2, a3, b0, b1) \
    asm volatile("mma.sync.aligned.m16n8k16.row.col.f32.bf16.bf16.f32 " \
        "{%0,%1,%2,%3}, {%4,%5,%6,%7}, {%8,%9}, {%0,%1,%2,%3};" \
        : "+f"((d)[0]), "+f"((d)[1]), "+f"((d)[2]), "+f"((d)[3]) \
        : "r"(a0), "r"(a1), "r"(a2), "r"(a3), "r"(b0), "r"(b1))

#define CP16(dst, src) \
    asm volatile("cp.async.cg.shared.global [%0], [%1], 16;" :: "r"(dst), "l"(src))
#define CP_COMMIT() asm volatile("cp.async.commit_group;" ::: "memory")
#define CP_WAIT1()  asm volatile("cp.async.wait_group 1;" ::: "memory")
#define CP_WAIT0()  asm volatile("cp.async.wait_group 0;" ::: "memory")

__device__ __forceinline__ void cvt_split4(float4 v, uint2& hi, uint2& lo) {
    __nv_bfloat16 a = __float2bfloat16(v.x), b = __float2bfloat16(v.y);
    __nv_bfloat16 c = __float2bfloat16(v.z), d = __float2bfloat16(v.w);
    __nv_bfloat162 h0; h0.x = a; h0.y = b;
    __nv_bfloat162 h1; h1.x = c; h1.y = d;
    hi = make_uint2(*(uint32_t*)&h0, *(uint32_t*)&h1);
    __nv_bfloat162 l0, l1;
    l0.x = __float2bfloat16(v.x - __bfloat162float(a));
    l0.y = __float2bfloat16(v.y - __bfloat162float(b));
    l1.x = __float2bfloat16(v.z - __bfloat162float(c));
    l1.y = __float2bfloat16(v.w - __bfloat162float(d));
    lo = make_uint2(*(uint32_t*)&l0, *(uint32_t*)&l1);
}
__device__ __forceinline__ void cvt_split2(float a, float b, uint32_t& hi, uint32_t& lo) {
    __nv_bfloat16 ha = __float2bfloat16(a), hb = __float2bfloat16(b);
    __nv_bfloat162 h; h.x = ha; h.y = hb;
    hi = *(uint32_t*)&h;
    __nv_bfloat162 l;
    l.x = __float2bfloat16(a - __bfloat162float(ha));
    l.y = __float2bfloat16(b - __bfloat162float(hb));
    lo = *(uint32_t*)&l;
}

__device__ __forceinline__ float* out_pixel_ptr(float* __restrict__ out, int m) {
    int b = m / 25600;
    int r = m % 25600;
    int w = r >> 6;
    int p = r & 63;
    int py = p >> 3, px = p & 7;
    if (w < N1) {
        int y = (w >> 4) * 8 + py, xx = (w & 15) * 8 + px;
        return out + ((size_t)((b * 128 + y) * 128 + xx)) * DIM;
    } else {
        int w2 = w - N1;
        int y = (w2 / 12) * 8 + py, xx = (w2 % 12) * 8 + px;
        return out + 16777216 + ((size_t)((b * 96 + y) * 96 + xx)) * DIM;
    }
}

// ============================================================================
// K0 v2: fused x split (bf16 hi/lo) + window mean.  One block per window.
// grid 1600, 256 threads.  Thread = (pixel-group pg: t>>6, dim-quad c: t&63).
// ============================================================================
__global__ __launch_bounds__(256) void k_xmean(const float* __restrict__ x1,
                                               const float* __restrict__ x2)
{
    int bw = blockIdx.x;
    int b = bw / NTOT, w = bw % NTOT;
    int t = threadIdx.x;
    int c = t & 63, pg = t >> 6;

    const float* xbase;
    __nv_bfloat16* dh;
    __nv_bfloat16* dl;
    int rowstride;
    if (w < N1) {
        int wy = w >> 4, wx = w & 15;
        size_t org = ((size_t)(b * 128 + wy * 8) * 128 + wx * 8) * 256;
        xbase = x1 + org;
        dh = g_x1h + org;
        dl = g_x1l + org;
        rowstride = 128 * 256;
    } else {
        int w2 = w - N1;
        int wy = w2 / 12, wx = w2 % 12;
        size_t org = ((size_t)(b * 96 + wy * 8) * 96 + wx * 8) * 256;
        xbase = x2 + org;
        dh = g_x2h + org;
        dl = g_x2l + org;
        rowstride = 96 * 256;
    }

    __shared__ __align__(16) float fpart[4][64][4];
    float4 s = make_float4(0.f, 0.f, 0.f, 0.f);
    #pragma unroll
    for (int i = 0; i < 16; ++i) {
        int p = pg * 16 + i;
        int py = p >> 3, px = p & 7;
        size_t off = (size_t)py * rowstride + px * 256 + c * 4;
        float4 v = *(const float4*)(xbase + off);
        uint2 hi, lo;
        cvt_split4(v, hi, lo);
        *(uint2*)(dh + off) = hi;
        *(uint2*)(dl + off) = lo;
        s.x += v.x; s.y += v.y; s.z += v.z; s.w += v.w;
    }
    *(float4*)fpart[pg][c] = s;
    __syncthreads();

    if (t < 64) {
        float4 p0 = *(const float4*)fpart[0][t];
        float4 p1 = *(const float4*)fpart[1][t];
        float4 p2 = *(const float4*)fpart[2][t];
        float4 p3 = *(const float4*)fpart[3][t];
        float4 m = make_float4((p0.x + p1.x + p2.x + p3.x) * (1.f / 64.f),
                               (p0.y + p1.y + p2.y + p3.y) * (1.f / 64.f),
                               (p0.z + p1.z + p2.z + p3.z) * (1.f / 64.f),
                               (p0.w + p1.w + p2.w + p3.w) * (1.f / 64.f));
        *(float4*)&g_favg[((size_t)(b * NTOT + w)) * 256 + t * 4] = m;
    }
}

// ============================================================================
// K1 v3: QK projection + RMS from precomputed means.  8 windows/block, grid 200.
// ============================================================================
__global__ __launch_bounds__(512) void k_embedp(
    const float* __restrict__ c1, const float* __restrict__ c2,
    const float* __restrict__ fqk_w, const float* __restrict__ fqk_b, const float* __restrict__ fqk_g,
    const float* __restrict__ cqk_w, const float* __restrict__ cqk_b, const float* __restrict__ cqk_g)
{
    int bw = blockIdx.x;
    int b = bw / 50, wg = (bw % 50) * 8;
    __shared__ __align__(16) float favg[8][256];
    __shared__ float cavg[8][4];
    __shared__ float redf[8][16];
    __shared__ float redc[8][4];
    int t = threadIdx.x;

    // load means: thread (q: t>>6, c: t&63) -> one float4
    {
        int q = t >> 6, c = t & 63;
        *(float4*)&favg[q][c * 4] =
            *(const float4*)&g_favg[((size_t)(b * NTOT + wg + q)) * 256 + c * 4];
    }
    // c means
    if (t < 32) {
        int q = t >> 2, ch = t & 3;
        int w = wg + q;
        const float* cbase;
        int crowstride;
        if (w < N1) {
            int wy = w >> 4, wx = w & 15;
            cbase = c1 + ((size_t)((b * 128 + wy * 8) * 128 + wx * 8)) * 4;
            crowstride = 128 * 4;
        } else {
            int w2 = w - N1;
            int wy = w2 / 12, wx = w2 % 12;
            cbase = c2 + ((size_t)((b * 96 + wy * 8) * 96 + wx * 8)) * 4;
            crowstride = 96 * 4;
        }
        float s = 0.f;
        #pragma unroll
        for (int py = 0; py < 8; ++py)
            #pragma unroll
            for (int px = 0; px < 8; ++px)
                s += cbase[py * crowstride + px * 4 + ch];
        cavg[q][ch] = s * (1.f / 64.f);
    }
    __syncthreads();

    const float4* fw = (const float4*)(fqk_w + (size_t)t * 256);
    float raw[8];
    float bias = fqk_b[t];
    #pragma unroll
    for (int q = 0; q < 8; ++q) raw[q] = bias;
    #pragma unroll 8
    for (int d4 = 0; d4 < 64; ++d4) {
        float4 wv = fw[d4];
        #pragma unroll
        for (int q = 0; q < 8; ++q) {
            float4 av = ((const float4*)favg[q])[d4];
            raw[q] += wv.x * av.x + wv.y * av.y + wv.z * av.z + wv.w * av.w;
        }
    }
    float rawc[8];
    if (t < 128) {
        float cb = cqk_b[t];
        float w0 = cqk_w[t * 4 + 0], w1 = cqk_w[t * 4 + 1];
        float w2 = cqk_w[t * 4 + 2], w3 = cqk_w[t * 4 + 3];
        #pragma unroll
        for (int q = 0; q < 8; ++q)
            rawc[q] = cb + cavg[q][0] * w0 + cavg[q][1] * w1 + cavg[q][2] * w2 + cavg[q][3] * w3;
    }

    #pragma unroll
    for (int q = 0; q < 8; ++q) {
        float sf = raw[q] * raw[q];
        #pragma unroll
        for (int o = 16; o; o >>= 1) sf += __shfl_xor_sync(~0u, sf, o);
        if ((t & 31) == 0) redf[q][t >> 5] = sf;
    }
    if (t < 128) {
        #pragma unroll
        for (int q = 0; q < 8; ++q) {
            float sc = rawc[q] * rawc[q];
            #pragma unroll
            for (int o = 16; o; o >>= 1) sc += __shfl_xor_sync(~0u, sc, o);
            if ((t & 31) == 0) redc[q][t >> 5] = sc;
        }
    }
    __syncthreads();

    float gain = fqk_g[t];
    #pragma unroll
    for (int q = 0; q < 8; ++q) {
        float msf = 0.f;
        #pragma unroll
        for (int i = 0; i < 16; ++i) msf += redf[q][i];
        float invf = rsqrtf(msf * (1.f / 512.f) + 1e-6f);
        g_fqk[((size_t)(b * NTOT + wg + q)) * 512 + t] = raw[q] * invf * gain;
    }
    if (t < 128) {
        float cg = cqk_g[t];
        #pragma unroll
        for (int q = 0; q < 8; ++q) {
            float msc = redc[q][0] + redc[q][1] + redc[q][2] + redc[q][3];
            float invc = rsqrtf(msc * (1.f / 128.f) + 1e-6f);
            g_cqk[((size_t)(b * NTOT + wg + q)) * 128 + t] = rawc[q] * invc * cg;
        }
    }
}

// ============================================================================
// K2: W2 = vb_w @ v_w  (256x256), bf16 hi/lo split
// ============================================================================
__global__ __launch_bounds__(256) void k_wmat(const float* __restrict__ vb_w,
                                              const float* __restrict__ v_w)
{
    int i = blockIdx.x, d = threadIdx.x;
    __shared__ float vb[256];
    vb[d] = vb_w[i * 256 + d];
    __syncthreads();
    float acc = 0.f;
    #pragma unroll 8
    for (int o = 0; o < 256; ++o) acc += vb[o] * v_w[o * 256 + d];
    __nv_bfloat16 h = __float2bfloat16(acc);
    g_w2h[i * 256 + d] = h;
    g_w2l[i * 256 + d] = __float2bfloat16(acc - __bfloat162float(h));
}

// ============================================================================
// K3 v2: scores + softmax, tiled.  Writes attn as bf16 hi/lo split.
// grid (7, 32), 512 threads = 64 rows x 8 lanes.
// ============================================================================
__global__ __launch_bounds__(512) void k_attn2()
{
    int tt = blockIdx.x;
    int bh = blockIdx.y;
    int b = bh >> 3, h = bh & 7;
    int n0 = tt * 64;
    int seg1 = (n0 >= N1);
    int colstart = seg1 ? 0 : N1;
    int cnt = seg1 ? N1 : N2;

    __shared__ __align__(16) float ksm[256][44];
    int t = threadIdx.x;

    for (int i = t; i < cnt * 10; i += 512) {
        int c = i / 10, j = i - c * 10;
        int mg = colstart + c;
        float4 v;
        if (j < 8)
            v = *(const float4*)(g_fqk + ((size_t)(b * NTOT + mg)) * 512 + 256 + h * 32 + j * 4);
        else
            v = *(const float4*)(g_cqk + ((size_t)(b * NTOT + mg)) * 128 + 64 + h * 8 + (j - 8) * 4);
        *(float4*)&ksm[c][j * 4] = v;
    }

    int r  = t >> 3;
    int cg = t & 7;
    int n = n0 + r;
    int nsafe = (n < NTOT) ? n : (NTOT - 1);
    float q[40];
    {
        const float* qf = g_fqk + ((size_t)(b * NTOT + nsafe)) * 512 + h * 32;
        const float* qc = g_cqk + ((size_t)(b * NTOT + nsafe)) * 128 + h * 8;
        #pragma unroll
        for (int i = 0; i < 32; ++i) q[i] = qf[i];
        #pragma unroll
        for (int i = 0; i < 8; ++i) q[32 + i] = qc[i];
    }
    __syncthreads();

    size_t dstbase = ((size_t)(bh * NTOT + nsafe)) * 256;
    bool wvalid = (n < NTOT);

    if (seg1) {
        float sc[32];
        float mx = -1e30f;
        #pragma unroll
        for (int it = 0; it < 32; ++it) {
            const float* kp = ksm[cg + it * 8];
            float s = 0.f, s2 = 0.f;
            #pragma unroll
            for (int i = 0; i < 32; ++i) s += q[i] * kp[i];
            #pragma unroll
            for (int i = 0; i < 8; ++i) s2 += q[32 + i] * kp[32 + i];
            float v = s * 0.1767766952966369f + s2 * 0.3535533905932738f;
            sc[it] = v;
            mx = fmaxf(mx, v);
        }
        #pragma unroll
        for (int o = 1; o < 8; o <<= 1) mx = fmaxf(mx, __shfl_xor_sync(~0u, mx, o));
        float sum = 0.f;
        #pragma unroll
        for (int it = 0; it < 32; ++it) { sc[it] = __expf(sc[it] - mx); sum += sc[it]; }
        #pragma unroll
        for (int o = 1; o < 8; o <<= 1) sum += __shfl_xor_sync(~0u, sum, o);
        float inv = 1.f / sum;
        if (wvalid) {
            #pragma unroll
            for (int it = 0; it < 32; ++it) {
                float p = sc[it] * inv;
                __nv_bfloat16 hh = __float2bfloat16(p);
                g_attnh[dstbase + cg + it * 8] = hh;
                g_attnl[dstbase + cg + it * 8] = __float2bfloat16(p - __bfloat162float(hh));
            }
        }
    } else {
        float sc[18];
        float mx = -1e30f;
        #pragma unroll
        for (int it = 0; it < 18; ++it) {
            const float* kp = ksm[cg + it * 8];
            float s = 0.f, s2 = 0.f;
            #pragma unroll
            for (int i = 0; i < 32; ++i) s += q[i] * kp[i];
            #pragma unroll
            for (int i = 0; i < 8; ++i) s2 += q[32 + i] * kp[32 + i];
            float v = s * 0.1767766952966369f + s2 * 0.3535533905932738f;
            sc[it] = v;
            mx = fmaxf(mx, v);
        }
        #pragma unroll
        for (int o = 1; o < 8; o <<= 1) mx = fmaxf(mx, __shfl_xor_sync(~0u, mx, o));
        float sum = 0.f;
        #pragma unroll
        for (int it = 0; it < 18; ++it) { sc[it] = __expf(sc[it] - mx); sum += sc[it]; }
        #pragma unroll
        for (int o = 1; o < 8; o <<= 1) sum += __shfl_xor_sync(~0u, sum, o);
        float inv = 1.f / sum;
        if (wvalid) {
            #pragma unroll
            for (int it = 0; it < 18; ++it) {
                float p = sc[it] * inv;
                __nv_bfloat16 hh = __float2bfloat16(p);
                g_attnh[dstbase + cg + it * 8] = hh;
                g_attnl[dstbase + cg + it * 8] = __float2bfloat16(p - __bfloat162float(hh));
            }
        }
    }
}

// ============================================================================
// K4 v6: mix = attn @ X via HMMA 3-split (R12/R14-measured).  Tile 64x256,
// 8 warps, K-chunk 32, double-buffered.  grid (8, 7, 32), 256 threads.
// ============================================================================
#define AV6_SMEM (20480 + 2 * 33792)   // 88064

__global__ __launch_bounds__(256)
void k_attnv6()
{
    extern __shared__ __align__(128) char sm[];
    uint32_t sb = smem_u32(sm);
    int tid = threadIdx.x;
    int lane = tid & 31, wid = tid >> 5;
    int wm = wid >> 2, wn = wid & 3;

    int bh = blockIdx.z;
    int b = bh >> 3, h = bh & 7;
    int n0 = blockIdx.y * 64;
    int j0 = blockIdx.x * 256;
    int seg1 = (n0 >= N1);
    int kExt = seg1 ? N1 : N2;
    int nkc = (kExt + 31) >> 5;           // 8 or 5

    int pp = 8 * h + blockIdx.x;          // pixel for this block
    int py = pp >> 3, px = pp & 7;
    const __nv_bfloat16* bsrcH;
    const __nv_bfloat16* bsrcL;
    int W;
    if (seg1) { bsrcH = g_x1h + (size_t)b * 4194304; bsrcL = g_x1l + (size_t)b * 4194304; W = 128; }
    else      { bsrcH = g_x2h + (size_t)b * 2359296; bsrcL = g_x2l + (size_t)b * 2359296; W = 96;  }

    int alrow = tid >> 2;
    int apart = (tid & 3) * 16;
    int aglob = n0 + alrow; if (aglob > NTOT - 1) aglob = NTOT - 1;
    const char* aSrcH = (const char*)(g_attnh + ((size_t)bh * NTOT + aglob) * 256) + apart;
    const char* aSrcL = (const char*)(g_attnl + ((size_t)bh * NTOT + aglob) * 256) + apart;
    uint32_t aDst = (uint32_t)(alrow * 80 + apart);

    int brow = tid >> 3;
    int bpart = (tid & 7) * 64;

    #define AV_ISSUE(st, kc) do { \
        uint32_t ad = sb + (st) * 10240 + aDst; \
        CP16(ad,        aSrcH + (kc) * 64); \
        CP16(ad + 5120, aSrcL + (kc) * 64); \
        int idx_ = (kc) * 32 + brow; if (idx_ > kExt - 1) idx_ = kExt - 1; \
        int wy_, wx_; \
        if (seg1) { wy_ = idx_ >> 4; wx_ = idx_ & 15; } \
        else      { wy_ = idx_ / 12; wx_ = idx_ - wy_ * 12; } \
        size_t off_ = ((size_t)((wy_ * 8 + py) * W + wx_ * 8 + px)) * 256; \
        const char* bh_ = (const char*)(bsrcH + off_) + bpart; \
        const char* bl_ = (const char*)(bsrcL + off_) + bpart; \
        uint32_t bd = sb + 20480 + (st) * 33792 + (uint32_t)(brow * 528 + bpart); \
        CP16(bd,      bh_);      CP16(bd + 16,      bh_ + 16); \
        CP16(bd + 32, bh_ + 32); CP16(bd + 48,      bh_ + 48); \
        CP16(bd + 16896,      bl_);      CP16(bd + 16896 + 16, bl_ + 16); \
        CP16(bd + 16896 + 32, bl_ + 32); CP16(bd + 16896 + 48, bl_ + 48); \
        CP_COMMIT(); \
    } while (0)

    AV_ISSUE(0, 0);
    AV_ISSUE(1, 1);

    float acc[2][8][4];
    #pragma unroll
    for (int mt = 0; mt < 2; ++mt)
        #pragma unroll
        for (int nt = 0; nt < 8; ++nt)
            #pragma unroll
            for (int q = 0; q < 4; ++q) acc[mt][nt][q] = 0.f;

    uint32_t lma_off = (uint32_t)((wm * 32 + (lane & 15)) * 80 + (lane >> 4) * 16);
    uint32_t lmb_off = (uint32_t)(((((lane >> 3) & 1) * 8 + (lane & 7)) * 528)
                                  + wn * 128 + (lane >> 4) * 16);

    for (int kc = 0; kc < nkc; ++kc) {
        if (kc == nkc - 1) { CP_WAIT0(); } else { CP_WAIT1(); }
        __syncthreads();
        int ksmax = (kExt - kc * 32 >= 32) ? 2 : 1;
        uint32_t aBase = sb + (uint32_t)((kc & 1) * 10240);
        uint32_t bBase = sb + 20480 + (uint32_t)((kc & 1) * 33792);
        for (int ks = 0; ks < ksmax; ++ks) {
            uint32_t ka = aBase + lma_off + ks * 32;
            uint32_t kb = bBase + lmb_off + ks * (16 * 528);
            uint32_t ah[2][4], al[2][4];
            LDSM_X4(ah[0][0], ah[0][1], ah[0][2], ah[0][3], ka);
            LDSM_X4(ah[1][0], ah[1][1], ah[1][2], ah[1][3], ka + 16 * 80);
            LDSM_X4(al[0][0], al[0][1], al[0][2], al[0][3], ka + 5120);
            LDSM_X4(al[1][0], al[1][1], al[1][2], al[1][3], ka + 5120 + 16 * 80);
            #pragma unroll
            for (int ng = 0; ng < 4; ++ng) {
                uint32_t bhf[4], blf[4];
                LDSM_X4_T(bhf[0], bhf[1], bhf[2], bhf[3], kb + ng * 32);
                LDSM_X4_T(blf[0], blf[1], blf[2], blf[3], kb + ng * 32 + 16896);
                #pragma unroll
                for (int hf = 0; hf < 2; ++hf) {
                    int nt = ng * 2 + hf;
                    uint32_t b0 = bhf[hf * 2], b1 = bhf[hf * 2 + 1];
                    uint32_t l0 = blf[hf * 2], l1 = blf[hf * 2 + 1];
                    #pragma unroll
                    for (int mt = 0; mt < 2; ++mt) {
                        MMA16816(acc[mt][nt], ah[mt][0], ah[mt][1], ah[mt][2], ah[mt][3], b0, b1);
                        MMA16816(acc[mt][nt], ah[mt][0], ah[mt][1], ah[mt][2], ah[mt][3], l0, l1);
                        MMA16816(acc[mt][nt], al[mt][0], al[mt][1], al[mt][2], al[mt][3], b0, b1);
                    }
                }
            }
        }
        __syncthreads();
        if (kc + 2 < nkc) AV_ISSUE(kc & 1, kc + 2);
    }
    #undef AV_ISSUE

    #pragma unroll
    for (int mt = 0; mt < 2; ++mt) {
        #pragma unroll
        for (int hrow = 0; hrow < 2; ++hrow) {
            int n = n0 + wm * 32 + mt * 16 + (lane >> 2) + hrow * 8;
            if (n < NTOT) {
                size_t idx = ((size_t)(b * NTOT + n)) * 16384 + h * 2048 + j0
                           + wn * 64 + (lane & 3) * 2;
                #pragma unroll
                for (int nt = 0; nt < 8; ++nt) {
                    uint32_t hi, lo;
                    cvt_split2(acc[mt][nt][hrow * 2 + 0], acc[mt][nt][hrow * 2 + 1], hi, lo);
                    *(uint32_t*)((char*)g_mixh + (idx + nt * 8) * 2) = hi;
                    *(uint32_t*)((char*)g_mixl + (idx + nt * 8) * 2) = lo;
                }
            }
        }
    }
}

// ============================================================================
// K5 v2: out = mix @ W2^T via HMMA — persistent W2 in smem (R10-measured).
// ============================================================================
#define PB_LO   81920
#define PA_BASE 163840
#define PSM_TOT 204800

__global__ __launch_bounds__(256, 1)
void k_proj2(float* __restrict__ Cout)
{
    extern __shared__ __align__(128) char sm[];
    uint32_t sb = smem_u32(sm);
    int tid = threadIdx.x;
    int lane = tid & 31, wid = tid >> 5;
    int wm = wid >> 1, wn = wid & 1;
    int n0 = blockIdx.x * 128;

    int lrow = tid >> 1;
    int half = tid & 1;
    uint32_t dbase = (uint32_t)(lrow * 80 + half * 32);

    {
        const char* ph = (const char*)g_w2h + ((size_t)(n0 + lrow) * 256 + half * 16) * 2;
        const char* pl = (const char*)g_w2l + ((size_t)(n0 + lrow) * 256 + half * 16) * 2;
        #pragma unroll
        for (int kc = 0; kc < 8; ++kc) {
            uint32_t d = sb + kc * 10240 + dbase;
            CP16(d,              ph + kc * 64);
            CP16(d + 16,         ph + kc * 64 + 16);
            CP16(d + PB_LO,      pl + kc * 64);
            CP16(d + PB_LO + 16, pl + kc * 64 + 16);
        }
        CP_COMMIT();
    }

    uint32_t lma_off = (uint32_t)(PA_BASE + (wm * 32 + (lane & 15)) * 80 + (lane >> 4) * 16);
    uint32_t lmb_off = (uint32_t)((wn * 64 + (lane & 7) + ((lane >> 4) & 1) * 8) * 80
                                  + ((lane >> 3) & 1) * 16);

    for (int mt = blockIdx.y; mt < 800; mt += (int)gridDim.y) {
        int m0 = mt * 128;
        const char* pAh = (const char*)g_mixh + ((size_t)(m0 + lrow) * 256 + half * 16) * 2;
        const char* pAl = (const char*)g_mixl + ((size_t)(m0 + lrow) * 256 + half * 16) * 2;

        #define AISSUE(st, kc) do { \
            uint32_t d0 = sb + PA_BASE + (st) * 20480 + dbase; \
            CP16(d0,              pAh + (kc) * 64); \
            CP16(d0 + 16,         pAh + (kc) * 64 + 16); \
            CP16(d0 + 10240,      pAl + (kc) * 64); \
            CP16(d0 + 10240 + 16, pAl + (kc) * 64 + 16); \
            CP_COMMIT(); \
        } while (0)

        AISSUE(0, 0);
        AISSUE(1, 1);

        float acc[2][8][4];
        #pragma unroll
        for (int mtt = 0; mtt < 2; ++mtt)
            #pragma unroll
            for (int nt = 0; nt < 8; ++nt)
                #pragma unroll
                for (int q = 0; q < 4; ++q) acc[mtt][nt][q] = 0.f;

        for (int kc = 0; kc < 8; ++kc) {
            if (kc == 7) { CP_WAIT0(); } else { CP_WAIT1(); }
            __syncthreads();
            uint32_t lm_a = sb + (uint32_t)((kc & 1) * 20480) + lma_off;
            uint32_t lm_b = sb + (uint32_t)(kc * 10240) + lmb_off;
            #pragma unroll
            for (int ks = 0; ks < 2; ++ks) {
                uint32_t ka = lm_a + ks * 32;
                uint32_t kb = lm_b + ks * 32;
                uint32_t ah[2][4], al[2][4];
                LDSM_X4(ah[0][0], ah[0][1], ah[0][2], ah[0][3], ka);
                LDSM_X4(ah[1][0], ah[1][1], ah[1][2], ah[1][3], ka + 16 * 80);
                LDSM_X4(al[0][0], al[0][1], al[0][2], al[0][3], ka + 10240);
                LDSM_X4(al[1][0], al[1][1], al[1][2], al[1][3], ka + 10240 + 16 * 80);
                #pragma unroll
                for (int ng = 0; ng < 4; ++ng) {
                    uint32_t bh[4], bl[4];
                    LDSM_X4(bh[0], bh[1], bh[2], bh[3], kb + ng * (16 * 80));
                    LDSM_X4(bl[0], bl[1], bl[2], bl[3], kb + ng * (16 * 80) + PB_LO);
                    #pragma unroll
                    for (int hf = 0; hf < 2; ++hf) {
                        int nt = ng * 2 + hf;
                        uint32_t b0 = bh[hf * 2], b1 = bh[hf * 2 + 1];
                        uint32_t l0 = bl[hf * 2], l1 = bl[hf * 2 + 1];
                        #pragma unroll
                        for (int mtt = 0; mtt < 2; ++mtt) {
                            MMA16816(acc[mtt][nt], ah[mtt][0], ah[mtt][1], ah[mtt][2], ah[mtt][3], b0, b1);
                            MMA16816(acc[mtt][nt], ah[mtt][0], ah[mtt][1], ah[mtt][2], ah[mtt][3], l0, l1);
                            MMA16816(acc[mtt][nt], al[mtt][0], al[mtt][1], al[mtt][2], al[mtt][3], b0, b1);
                        }
                    }
                }
            }
            __syncthreads();
            if (kc + 2 < 8) AISSUE(kc & 1, kc + 2);
        }
        #undef AISSUE

        #pragma unroll
        for (int mtt = 0; mtt < 2; ++mtt) {
            #pragma unroll
            for (int hrow = 0; hrow < 2; ++hrow) {
                int m = m0 + wm * 32 + mtt * 16 + (lane >> 2) + hrow * 8;
                float* dst = out_pixel_ptr(Cout, m) + n0 + wn * 64 + (lane & 3) * 2;
                #pragma unroll
                for (int nt = 0; nt < 8; ++nt) {
                    float2 v = make_float2(acc[mtt][nt][hrow * 2 + 0], acc[mtt][nt][hrow * 2 + 1]);
                    *(float2*)(dst + nt * 8) = v;
                }
            }
        }
    }
}

// ============================================================================
extern "C" void kernel_launch(void* const* d_in, const int* in_sizes, int n_in,
                              void* d_out, int out_size)
{
    const float* x1    = (const float*)d_in[0];
    const float* c1    = (const float*)d_in[1];
    const float* x2    = (const float*)d_in[2];
    const float* c2    = (const float*)d_in[3];
    const float* fqk_w = (const float*)d_in[4];
    const float* fqk_b = (const float*)d_in[5];
    const float* fqk_g = (const float*)d_in[6];
    const float* cqk_w = (const float*)d_in[7];
    const float* cqk_b = (const float*)d_in[8];
    const float* cqk_g = (const float*)d_in[9];
    const float* v_w   = (const float*)d_in[10];
    const float* vb_w  = (const float*)d_in[11];
    float* out = (float*)d_out;

    static cudaStream_t s_side = nullptr;
    static cudaEvent_t e_fork = nullptr, e_join = nullptr;
    static bool attr_set = false;
    if (!attr_set) {
        cudaFuncSetAttribute(k_proj2, cudaFuncAttributeMaxDynamicSharedMemorySize, PSM_TOT);
        cudaFuncSetAttribute(k_attnv6, cudaFuncAttributeMaxDynamicSharedMemorySize, AV6_SMEM);
        cudaStreamCreateWithFlags(&s_side, cudaStreamNonBlocking);
        cudaEventCreateWithFlags(&e_fork, cudaEventDisableTiming);
        cudaEventCreateWithFlags(&e_join, cudaEventDisableTiming);
        attr_set = true;
    }

    // fork: side stream runs wmat concurrently with the main chain
    cudaEventRecord(e_fork, 0);
    cudaStreamWaitEvent(s_side, e_fork, 0);
    k_wmat<<<256, 256, 0, s_side>>>(vb_w, v_w);
    cudaEventRecord(e_join, s_side);

    // main chain: fused split+mean -> projection -> softmax -> GEMMs
    k_xmean<<<1600, 256>>>(x1, x2);
    k_embedp<<<200, 512>>>(c1, c2, fqk_w, fqk_b, fqk_g, cqk_w, cqk_b, cqk_g);
    k_attn2<<<dim3(7, 32), 512>>>();

    cudaStreamWaitEvent(0, e_join, 0);
    k_attnv6<<<dim3(8, 7, 32), 256, AV6_SMEM>>>();
    k_proj2<<<dim3(2, 148), 256, PSM_TOT>>>(out);
}

// round 16
// speedup vs baseline: 1.2130x; 1.2130x over previous
#include <cuda_runtime.h>
#include <cuda_bf16.h>
#include <cuda_fp16.h>
#include <cstdint>
#include <math.h>

// ---- problem constants ----
#define B_    4
#define NTOT  400
#define N1    256
#define N2    144
#define DIM   256
#define NH    8

// ---- scratch ----
__device__ float g_fqk[B_ * NTOT * 512];
__device__ float g_cqk[B_ * NTOT * 128];
__device__ __half g_attnf[B_ * NH * NTOT * 256];  // attn fp16 (cols>=cnt stay 0)
__device__ __half g_x1f[16777216];                // x1 fp16
__device__ __half g_x2f[9437184];                 // x2 fp16
__device__ __nv_bfloat16 g_mixh[26214400];   // attn-mixed x, bf16 hi
__device__ __nv_bfloat16 g_mixl[26214400];   // bf16 lo residual
__device__ __nv_bfloat16 g_w2h[65536];       // W2 = vb_w @ v_w, bf16 hi
__device__ __nv_bfloat16 g_w2l[65536];       // bf16 lo

// ============================================================================
// helpers
// ============================================================================
__device__ __forceinline__ uint32_t smem_u32(const void* p) {
    uint32_t a;
    asm("{ .reg .u64 t; cvta.to.shared.u64 t, %1; cvt.u32.u64 %0, t; }" : "=r"(a) : "l"(p));
    return a;
}

#define LDSM_X4(r0, r1, r2, r3, addr) \
    asm volatile("ldmatrix.sync.aligned.m8n8.x4.shared.b16 {%0,%1,%2,%3}, [%4];" \
        : "=r"(r0), "=r"(r1), "=r"(r2), "=r"(r3) : "r"(addr))

#define LDSM_X4_T(r0, r1, r2, r3, addr) \
    asm volatile("ldmatrix.sync.aligned.m8n8.x4.trans.shared.b16 {%0,%1,%2,%3}, [%4];" \
        : "=r"(r0), "=r"(r1), "=r"(r2), "=r"(r3) : "r"(addr))

// bf16 MMA (proj)
#define MMA16816(d, a0, a1, a2, a3, b0, b1) \
    asm volatile("mma.sync.aligned.m16n8k16.row.col.f32.bf16.bf16.f32 " \
        "{%0,%1,%2,%3}, {%4,%5,%6,%7}, {%8,%9}, {%0,%1,%2,%3};" \
        : "+f"((d)[0]), "+f"((d)[1]), "+f"((d)[2]), "+f"((d)[3]) \
        : "r"(a0), "r"(a1), "r"(a2), "r"(a3), "r"(b0), "r"(b1))

// fp16 MMA (attnv)
#define MMA16816F(d, a0, a1, a2, a3, b0, b1) \
    asm volatile("mma.sync.aligned.m16n8k16.row.col.f32.f16.f16.f32 " \
        "{%0,%1,%2,%3}, {%4,%5,%6,%7}, {%8,%9}, {%0,%1,%2,%3};" \
        : "+f"((d)[0]), "+f"((d)[1]), "+f"((d)[2]), "+f"((d)[3]) \
        : "r"(a0), "r"(a1), "r"(a2), "r"(a3), "r"(b0), "r"(b1))

#define CP16(dst, src) \
    asm volatile("cp.async.cg.shared.global [%0], [%1], 16;" :: "r"(dst), "l"(src))
#define CP_COMMIT() asm volatile("cp.async.commit_group;" ::: "memory")
#define CP_WAIT1()  asm volatile("cp.async.wait_group 1;" ::: "memory")
#define CP_WAIT0()  asm volatile("cp.async.wait_group 0;" ::: "memory")

__device__ __forceinline__ void cvt_split2(float a, float b, uint32_t& hi, uint32_t& lo) {
    __nv_bfloat16 ha = __float2bfloat16(a), hb = __float2bfloat16(b);
    __nv_bfloat162 h; h.x = ha; h.y = hb;
    hi = *(uint32_t*)&h;
    __nv_bfloat162 l;
    l.x = __float2bfloat16(a - __bfloat162float(ha));
    l.y = __float2bfloat16(b - __bfloat162float(hb));
    lo = *(uint32_t*)&l;
}

__device__ __forceinline__ float* out_pixel_ptr(float* __restrict__ out, int m) {
    int b = m / 25600;
    int r = m % 25600;
    int w = r >> 6;
    int p = r & 63;
    int py = p >> 3, px = p & 7;
    if (w < N1) {
        int y = (w >> 4) * 8 + py, xx = (w & 15) * 8 + px;
        return out + ((size_t)((b * 128 + y) * 128 + xx)) * DIM;
    } else {
        int w2 = w - N1;
        int y = (w2 / 12) * 8 + py, xx = (w2 % 12) * 8 + px;
        return out + 16777216 + ((size_t)((b * 96 + y) * 96 + xx)) * DIM;
    }
}

// ============================================================================
// K0: convert x to fp16 (sel 0 -> g_x1f, 1 -> g_x2f).  Side-stream.
// ============================================================================
__global__ __launch_bounds__(256) void k_xhalf(const float4* __restrict__ src, int sel, int n4)
{
    __half2* d = (sel == 0) ? (__half2*)g_x1f : (__half2*)g_x2f;
    for (int i = blockIdx.x * 256 + threadIdx.x; i < n4; i += gridDim.x * 256) {
        float4 v = src[i];
        d[i * 2 + 0] = __floats2half2_rn(v.x, v.y);
        d[i * 2 + 1] = __floats2half2_rn(v.z, v.w);
    }
}

// ============================================================================
// K1 (R14-measured): window means -> QK proj -> RMS.  8 windows/block, grid 200.
// ============================================================================
__global__ __launch_bounds__(512) void k_embed8(
    const float* __restrict__ x1, const float* __restrict__ c1,
    const float* __restrict__ x2, const float* __restrict__ c2,
    const float* __restrict__ fqk_w, const float* __restrict__ fqk_b, const float* __restrict__ fqk_g,
    const float* __restrict__ cqk_w, const float* __restrict__ cqk_b, const float* __restrict__ cqk_g)
{
    int bw = blockIdx.x;
    int b = bw / 50, wg = (bw % 50) * 8;
    __shared__ __align__(16) float favg[8][256];
    __shared__ float cavg[8][4];
    __shared__ float redf[8][16];
    __shared__ float redc[8][4];
    int t = threadIdx.x;

    {
        int q = t >> 6, c = t & 63;
        int w = wg + q;
        const float* xbase;
        int rowstride;
        if (w < N1) {
            int wy = w >> 4, wx = w & 15;
            xbase = x1 + ((size_t)((b * 128 + wy * 8) * 128 + wx * 8)) * DIM;
            rowstride = 128 * DIM;
        } else {
            int w2 = w - N1;
            int wy = w2 / 12, wx = w2 % 12;
            xbase = x2 + ((size_t)((b * 96 + wy * 8) * 96 + wx * 8)) * DIM;
            rowstride = 96 * DIM;
        }
        const float* base = xbase + c * 4;
        float4 s = make_float4(0.f, 0.f, 0.f, 0.f);
        #pragma unroll
        for (int py = 0; py < 8; ++py)
            #pragma unroll
            for (int px = 0; px < 8; ++px) {
                float4 v = *(const float4*)(base + py * rowstride + px * DIM);
                s.x += v.x; s.y += v.y; s.z += v.z; s.w += v.w;
            }
        s.x *= (1.f / 64.f); s.y *= (1.f / 64.f); s.z *= (1.f / 64.f); s.w *= (1.f / 64.f);
        *(float4*)&favg[q][c * 4] = s;
    }
    if (t < 32) {
        int q = t >> 2, ch = t & 3;
        int w = wg + q;
        const float* cbase;
        int crowstride;
        if (w < N1) {
            int wy = w >> 4, wx = w & 15;
            cbase = c1 + ((size_t)((b * 128 + wy * 8) * 128 + wx * 8)) * 4;
            crowstride = 128 * 4;
        } else {
            int w2 = w - N1;
            int wy = w2 / 12, wx = w2 % 12;
            cbase = c2 + ((size_t)((b * 96 + wy * 8) * 96 + wx * 8)) * 4;
            crowstride = 96 * 4;
        }
        float s = 0.f;
        #pragma unroll
        for (int py = 0; py < 8; ++py)
            #pragma unroll
            for (int px = 0; px < 8; ++px)
                s += cbase[py * crowstride + px * 4 + ch];
        cavg[q][ch] = s * (1.f / 64.f);
    }
    __syncthreads();

    const float4* fw = (const float4*)(fqk_w + (size_t)t * 256);
    float raw[8];
    float bias = fqk_b[t];
    #pragma unroll
    for (int q = 0; q < 8; ++q) raw[q] = bias;
    #pragma unroll 8
    for (int d4 = 0; d4 < 64; ++d4) {
        float4 wv = fw[d4];
        #pragma unroll
        for (int q = 0; q < 8; ++q) {
            float4 av = ((const float4*)favg[q])[d4];
            raw[q] += wv.x * av.x + wv.y * av.y + wv.z * av.z + wv.w * av.w;
        }
    }
    float rawc[8];
    if (t < 128) {
        float cb = cqk_b[t];
        float w0 = cqk_w[t * 4 + 0], w1 = cqk_w[t * 4 + 1];
        float w2 = cqk_w[t * 4 + 2], w3 = cqk_w[t * 4 + 3];
        #pragma unroll
        for (int q = 0; q < 8; ++q)
            rawc[q] = cb + cavg[q][0] * w0 + cavg[q][1] * w1 + cavg[q][2] * w2 + cavg[q][3] * w3;
    }

    #pragma unroll
    for (int q = 0; q < 8; ++q) {
        float sf = raw[q] * raw[q];
        #pragma unroll
        for (int o = 16; o; o >>= 1) sf += __shfl_xor_sync(~0u, sf, o);
        if ((t & 31) == 0) redf[q][t >> 5] = sf;
    }
    if (t < 128) {
        #pragma unroll
        for (int q = 0; q < 8; ++q) {
            float sc = rawc[q] * rawc[q];
            #pragma unroll
            for (int o = 16; o; o >>= 1) sc += __shfl_xor_sync(~0u, sc, o);
            if ((t & 31) == 0) redc[q][t >> 5] = sc;
        }
    }
    __syncthreads();

    float gain = fqk_g[t];
    #pragma unroll
    for (int q = 0; q < 8; ++q) {
        float msf = 0.f;
        #pragma unroll
        for (int i = 0; i < 16; ++i) msf += redf[q][i];
        float invf = rsqrtf(msf * (1.f / 512.f) + 1e-6f);
        g_fqk[((size_t)(b * NTOT + wg + q)) * 512 + t] = raw[q] * invf * gain;
    }
    if (t < 128) {
        float cg = cqk_g[t];
        #pragma unroll
        for (int q = 0; q < 8; ++q) {
            float msc = redc[q][0] + redc[q][1] + redc[q][2] + redc[q][3];
            float invc = rsqrtf(msc * (1.f / 128.f) + 1e-6f);
            g_cqk[((size_t)(b * NTOT + wg + q)) * 128 + t] = rawc[q] * invc * cg;
        }
    }
}

// ============================================================================
// K2: W2 = vb_w @ v_w  (256x256), bf16 hi/lo split
// ============================================================================
__global__ __launch_bounds__(256) void k_wmat(const float* __restrict__ vb_w,
                                              const float* __restrict__ v_w)
{
    int i = blockIdx.x, d = threadIdx.x;
    __shared__ float vb[256];
    vb[d] = vb_w[i * 256 + d];
    __syncthreads();
    float acc = 0.f;
    #pragma unroll 8
    for (int o = 0; o < 256; ++o) acc += vb[o] * v_w[o * 256 + d];
    __nv_bfloat16 h = __float2bfloat16(acc);
    g_w2h[i * 256 + d] = h;
    g_w2l[i * 256 + d] = __float2bfloat16(acc - __bfloat162float(h));
}

// ============================================================================
// K3 v3: scores + softmax, tiled.  Writes attn as fp16.
// grid (7, 32), 512 threads = 64 rows x 8 lanes.
// ============================================================================
__global__ __launch_bounds__(512) void k_attn3()
{
    int tt = blockIdx.x;
    int bh = blockIdx.y;
    int b = bh >> 3, h = bh & 7;
    int n0 = tt * 64;
    int seg1 = (n0 >= N1);
    int colstart = seg1 ? 0 : N1;
    int cnt = seg1 ? N1 : N2;

    __shared__ __align__(16) float ksm[256][44];
    int t = threadIdx.x;

    for (int i = t; i < cnt * 10; i += 512) {
        int c = i / 10, j = i - c * 10;
        int mg = colstart + c;
        float4 v;
        if (j < 8)
            v = *(const float4*)(g_fqk + ((size_t)(b * NTOT + mg)) * 512 + 256 + h * 32 + j * 4);
        else
            v = *(const float4*)(g_cqk + ((size_t)(b * NTOT + mg)) * 128 + 64 + h * 8 + (j - 8) * 4);
        *(float4*)&ksm[c][j * 4] = v;
    }

    int r  = t >> 3;
    int cg = t & 7;
    int n = n0 + r;
    int nsafe = (n < NTOT) ? n : (NTOT - 1);
    float q[40];
    {
        const float* qf = g_fqk + ((size_t)(b * NTOT + nsafe)) * 512 + h * 32;
        const float* qc = g_cqk + ((size_t)(b * NTOT + nsafe)) * 128 + h * 8;
        #pragma unroll
        for (int i = 0; i < 32; ++i) q[i] = qf[i];
        #pragma unroll
        for (int i = 0; i < 8; ++i) q[32 + i] = qc[i];
    }
    __syncthreads();

    size_t dstbase = ((size_t)(bh * NTOT + nsafe)) * 256;
    bool wvalid = (n < NTOT);

    if (seg1) {
        float sc[32];
        float mx = -1e30f;
        #pragma unroll
        for (int it = 0; it < 32; ++it) {
            const float* kp = ksm[cg + it * 8];
            float s = 0.f, s2 = 0.f;
            #pragma unroll
            for (int i = 0; i < 32; ++i) s += q[i] * kp[i];
            #pragma unroll
            for (int i = 0; i < 8; ++i) s2 += q[32 + i] * kp[32 + i];
            float v = s * 0.1767766952966369f + s2 * 0.3535533905932738f;
            sc[it] = v;
            mx = fmaxf(mx, v);
        }
        #pragma unroll
        for (int o = 1; o < 8; o <<= 1) mx = fmaxf(mx, __shfl_xor_sync(~0u, mx, o));
        float sum = 0.f;
        #pragma unroll
        for (int it = 0; it < 32; ++it) { sc[it] = __expf(sc[it] - mx); sum += sc[it]; }
        #pragma unroll
        for (int o = 1; o < 8; o <<= 1) sum += __shfl_xor_sync(~0u, sum, o);
        float inv = 1.f / sum;
        if (wvalid) {
            #pragma unroll
            for (int it = 0; it < 32; ++it)
                g_attnf[dstbase + cg + it * 8] = __float2half_rn(sc[it] * inv);
        }
    } else {
        float sc[18];
        float mx = -1e30f;
        #pragma unroll
        for (int it = 0; it < 18; ++it) {
            const float* kp = ksm[cg + it * 8];
            float s = 0.f, s2 = 0.f;
            #pragma unroll
            for (int i = 0; i < 32; ++i) s += q[i] * kp[i];
            #pragma unroll
            for (int i = 0; i < 8; ++i) s2 += q[32 + i] * kp[32 + i];
            float v = s * 0.1767766952966369f + s2 * 0.3535533905932738f;
            sc[it] = v;
            mx = fmaxf(mx, v);
        }
        #pragma unroll
        for (int o = 1; o < 8; o <<= 1) mx = fmaxf(mx, __shfl_xor_sync(~0u, mx, o));
        float sum = 0.f;
        #pragma unroll
        for (int it = 0; it < 18; ++it) { sc[it] = __expf(sc[it] - mx); sum += sc[it]; }
        #pragma unroll
        for (int o = 1; o < 8; o <<= 1) sum += __shfl_xor_sync(~0u, sum, o);
        float inv = 1.f / sum;
        if (wvalid) {
            #pragma unroll
            for (int it = 0; it < 18; ++it)
                g_attnf[dstbase + cg + it * 8] = __float2half_rn(sc[it] * inv);
        }
    }
}

// ============================================================================
// K4 v8: mix = attn @ X via SINGLE-product fp16 HMMA.  Tile 64x256 (one pixel),
// 8 warps (32x64 each), K-chunk 32, double-buffered.  grid (8, 7, 32), 256 thr.
// smem: A 2st x 5120 @0 ; B 2st x 16896 @10240.  Total 44032 -> 2 CTAs/SM.
// ============================================================================
#define AV8_SMEM (10240 + 2 * 16896)   // 44032

__global__ __launch_bounds__(256)
void k_attnv8()
{
    extern __shared__ __align__(128) char sm[];
    uint32_t sb = smem_u32(sm);
    int tid = threadIdx.x;
    int lane = tid & 31, wid = tid >> 5;
    int wm = wid >> 2, wn = wid & 3;

    int bh = blockIdx.z;
    int b = bh >> 3, h = bh & 7;
    int n0 = blockIdx.y * 64;
    int j0 = blockIdx.x * 256;
    int seg1 = (n0 >= N1);
    int kExt = seg1 ? N1 : N2;
    int nkc = (kExt + 31) >> 5;           // 8 or 5

    int pp = 8 * h + blockIdx.x;          // pixel for this block
    int py = pp >> 3, px = pp & 7;
    const __half* bsrc;
    int W;
    if (seg1) { bsrc = g_x1f + (size_t)b * 4194304; W = 128; }
    else      { bsrc = g_x2f + (size_t)b * 2359296; W = 96;  }

    // A loader: row tid>>2 (0..63), 16B part (tid&3)
    int alrow = tid >> 2;
    int apart = (tid & 3) * 16;
    int aglob = n0 + alrow; if (aglob > NTOT - 1) aglob = NTOT - 1;
    const char* aSrc = (const char*)(g_attnf + ((size_t)bh * NTOT + aglob) * 256) + apart;
    uint32_t aDst = (uint32_t)(alrow * 80 + apart);

    // B loader: row tid>>3 (0..31), 64B part (tid&7)
    int brow = tid >> 3;
    int bpart = (tid & 7) * 64;

    #define AV_ISSUE(st, kc) do { \
        uint32_t ad = sb + (st) * 5120 + aDst; \
        CP16(ad, aSrc + (kc) * 64); \
        int idx_ = (kc) * 32 + brow; if (idx_ > kExt - 1) idx_ = kExt - 1; \
        int wy_, wx_; \
        if (seg1) { wy_ = idx_ >> 4; wx_ = idx_ & 15; } \
        else      { wy_ = idx_ / 12; wx_ = idx_ - wy_ * 12; } \
        size_t off_ = ((size_t)((wy_ * 8 + py) * W + wx_ * 8 + px)) * 256; \
        const char* bs_ = (const char*)(bsrc + off_) + bpart; \
        uint32_t bd = sb + 10240 + (st) * 16896 + (uint32_t)(brow * 528 + bpart); \
        CP16(bd,      bs_);      CP16(bd + 16, bs_ + 16); \
        CP16(bd + 32, bs_ + 32); CP16(bd + 48, bs_ + 48); \
        CP_COMMIT(); \
    } while (0)

    AV_ISSUE(0, 0);
    AV_ISSUE(1, 1);

    float acc[2][8][4];
    #pragma unroll
    for (int mt = 0; mt < 2; ++mt)
        #pragma unroll
        for (int nt = 0; nt < 8; ++nt)
            #pragma unroll
            for (int q = 0; q < 4; ++q) acc[mt][nt][q] = 0.f;

    uint32_t lma_off = (uint32_t)((wm * 32 + (lane & 15)) * 80 + (lane >> 4) * 16);
    uint32_t lmb_off = (uint32_t)(((((lane >> 3) & 1) * 8 + (lane & 7)) * 528)
                                  + wn * 128 + (lane >> 4) * 16);

    for (int kc = 0; kc < nkc; ++kc) {
        if (kc == nkc - 1) { CP_WAIT0(); } else { CP_WAIT1(); }
        __syncthreads();
        int ksmax = (kExt - kc * 32 >= 32) ? 2 : 1;
        uint32_t aBase = sb + (uint32_t)((kc & 1) * 5120);
        uint32_t bBase = sb + 10240 + (uint32_t)((kc & 1) * 16896);
        for (int ks = 0; ks < ksmax; ++ks) {
            uint32_t ka = aBase + lma_off + ks * 32;
            uint32_t kb = bBase + lmb_off + ks * (16 * 528);
            uint32_t ah[2][4];
            LDSM_X4(ah[0][0], ah[0][1], ah[0][2], ah[0][3], ka);
            LDSM_X4(ah[1][0], ah[1][1], ah[1][2], ah[1][3], ka + 16 * 80);
            #pragma unroll
            for (int ng = 0; ng < 4; ++ng) {
                uint32_t bf[4];
                LDSM_X4_T(bf[0], bf[1], bf[2], bf[3], kb + ng * 32);
                #pragma unroll
                for (int hf = 0; hf < 2; ++hf) {
                    int nt = ng * 2 + hf;
                    uint32_t b0 = bf[hf * 2], b1 = bf[hf * 2 + 1];
                    #pragma unroll
                    for (int mt = 0; mt < 2; ++mt)
                        MMA16816F(acc[mt][nt], ah[mt][0], ah[mt][1], ah[mt][2], ah[mt][3], b0, b1);
                }
            }
        }
        __syncthreads();
        if (kc + 2 < nkc) AV_ISSUE(kc & 1, kc + 2);
    }
    #undef AV_ISSUE

    // epilogue -> bf16 hi/lo split for proj
    #pragma unroll
    for (int mt = 0; mt < 2; ++mt) {
        #pragma unroll
        for (int hrow = 0; hrow < 2; ++hrow) {
            int n = n0 + wm * 32 + mt * 16 + (lane >> 2) + hrow * 8;
            if (n < NTOT) {
                size_t idx = ((size_t)(b * NTOT + n)) * 16384 + h * 2048 + j0
                           + wn * 64 + (lane & 3) * 2;
                #pragma unroll
                for (int nt = 0; nt < 8; ++nt) {
                    uint32_t hi, lo;
                    cvt_split2(acc[mt][nt][hrow * 2 + 0], acc[mt][nt][hrow * 2 + 1], hi, lo);
                    *(uint32_t*)((char*)g_mixh + (idx + nt * 8) * 2) = hi;
                    *(uint32_t*)((char*)g_mixl + (idx + nt * 8) * 2) = lo;
                }
            }
        }
    }
}

// ============================================================================
// K5 v2: out = mix @ W2^T via HMMA — persistent W2 in smem (R10-measured).
// ============================================================================
#define PB_LO   81920
#define PA_BASE 163840
#define PSM_TOT 204800

__global__ __launch_bounds__(256, 1)
void k_proj2(float* __restrict__ Cout)
{
    extern __shared__ __align__(128) char sm[];
    uint32_t sb = smem_u32(sm);
    int tid = threadIdx.x;
    int lane = tid & 31, wid = tid >> 5;
    int wm = wid >> 1, wn = wid & 1;
    int n0 = blockIdx.x * 128;

    int lrow = tid >> 1;
    int half = tid & 1;
    uint32_t dbase = (uint32_t)(lrow * 80 + half * 32);

    {
        const char* ph = (const char*)g_w2h + ((size_t)(n0 + lrow) * 256 + half * 16) * 2;
        const char* pl = (const char*)g_w2l + ((size_t)(n0 + lrow) * 256 + half * 16) * 2;
        #pragma unroll
        for (int kc = 0; kc < 8; ++kc) {
            uint32_t d = sb + kc * 10240 + dbase;
            CP16(d,              ph + kc * 64);
            CP16(d + 16,         ph + kc * 64 + 16);
            CP16(d + PB_LO,      pl + kc * 64);
            CP16(d + PB_LO + 16, pl + kc * 64 + 16);
        }
        CP_COMMIT();
    }

    uint32_t lma_off = (uint32_t)(PA_BASE + (wm * 32 + (lane & 15)) * 80 + (lane >> 4) * 16);
    uint32_t lmb_off = (uint32_t)((wn * 64 + (lane & 7) + ((lane >> 4) & 1) * 8) * 80
                                  + ((lane >> 3) & 1) * 16);

    for (int mt = blockIdx.y; mt < 800; mt += (int)gridDim.y) {
        int m0 = mt * 128;
        const char* pAh = (const char*)g_mixh + ((size_t)(m0 + lrow) * 256 + half * 16) * 2;
        const char* pAl = (const char*)g_mixl + ((size_t)(m0 + lrow) * 256 + half * 16) * 2;

        #define AISSUE(st, kc) do { \
            uint32_t d0 = sb + PA_BASE + (st) * 20480 + dbase; \
            CP16(d0,              pAh + (kc) * 64); \
            CP16(d0 + 16,         pAh + (kc) * 64 + 16); \
            CP16(d0 + 10240,      pAl + (kc) * 64); \
            CP16(d0 + 10240 + 16, pAl + (kc) * 64 + 16); \
            CP_COMMIT(); \
        } while (0)

        AISSUE(0, 0);
        AISSUE(1, 1);

        float acc[2][8][4];
        #pragma unroll
        for (int mtt = 0; mtt < 2; ++mtt)
            #pragma unroll
            for (int nt = 0; nt < 8; ++nt)
                #pragma unroll
                for (int q = 0; q < 4; ++q) acc[mtt][nt][q] = 0.f;

        for (int kc = 0; kc < 8; ++kc) {
            if (kc == 7) { CP_WAIT0(); } else { CP_WAIT1(); }
            __syncthreads();
            uint32_t lm_a = sb + (uint32_t)((kc & 1) * 20480) + lma_off;
            uint32_t lm_b = sb + (uint32_t)(kc * 10240) + lmb_off;
            #pragma unroll
            for (int ks = 0; ks < 2; ++ks) {
                uint32_t ka = lm_a + ks * 32;
                uint32_t kb = lm_b + ks * 32;
                uint32_t ah[2][4], al[2][4];
                LDSM_X4(ah[0][0], ah[0][1], ah[0][2], ah[0][3], ka);
                LDSM_X4(ah[1][0], ah[1][1], ah[1][2], ah[1][3], ka + 16 * 80);
                LDSM_X4(al[0][0], al[0][1], al[0][2], al[0][3], ka + 10240);
                LDSM_X4(al[1][0], al[1][1], al[1][2], al[1][3], ka + 10240 + 16 * 80);
                #pragma unroll
                for (int ng = 0; ng < 4; ++ng) {
                    uint32_t bh[4], bl[4];
                    LDSM_X4(bh[0], bh[1], bh[2], bh[3], kb + ng * (16 * 80));
                    LDSM_X4(bl[0], bl[1], bl[2], bl[3], kb + ng * (16 * 80) + PB_LO);
                    #pragma unroll
                    for (int hf = 0; hf < 2; ++hf) {
                        int nt = ng * 2 + hf;
                        uint32_t b0 = bh[hf * 2], b1 = bh[hf * 2 + 1];
                        uint32_t l0 = bl[hf * 2], l1 = bl[hf * 2 + 1];
                        #pragma unroll
                        for (int mtt = 0; mtt < 2; ++mtt) {
                            MMA16816(acc[mtt][nt], ah[mtt][0], ah[mtt][1], ah[mtt][2], ah[mtt][3], b0, b1);
                            MMA16816(acc[mtt][nt], ah[mtt][0], ah[mtt][1], ah[mtt][2], ah[mtt][3], l0, l1);
                            MMA16816(acc[mtt][nt], al[mtt][0], al[mtt][1], al[mtt][2], al[mtt][3], b0, b1);
                        }
                    }
                }
            }
            __syncthreads();
            if (kc + 2 < 8) AISSUE(kc & 1, kc + 2);
        }
        #undef AISSUE

        #pragma unroll
        for (int mtt = 0; mtt < 2; ++mtt) {
            #pragma unroll
            for (int hrow = 0; hrow < 2; ++hrow) {
                int m = m0 + wm * 32 + mtt * 16 + (lane >> 2) + hrow * 8;
                float* dst = out_pixel_ptr(Cout, m) + n0 + wn * 64 + (lane & 3) * 2;
                #pragma unroll
                for (int nt = 0; nt < 8; ++nt) {
                    float2 v = make_float2(acc[mtt][nt][hrow * 2 + 0], acc[mtt][nt][hrow * 2 + 1]);
                    *(float2*)(dst + nt * 8) = v;
                }
            }
        }
    }
}

// ============================================================================
extern "C" void kernel_launch(void* const* d_in, const int* in_sizes, int n_in,
                              void* d_out, int out_size)
{
    const float* x1    = (const float*)d_in[0];
    const float* c1    = (const float*)d_in[1];
    const float* x2    = (const float*)d_in[2];
    const float* c2    = (const float*)d_in[3];
    const float* fqk_w = (const float*)d_in[4];
    const float* fqk_b = (const float*)d_in[5];
    const float* fqk_g = (const float*)d_in[6];
    const float* cqk_w = (const float*)d_in[7];
    const float* cqk_b = (const float*)d_in[8];
    const float* cqk_g = (const float*)d_in[9];
    const float* v_w   = (const float*)d_in[10];
    const float* vb_w  = (const float*)d_in[11];
    float* out = (float*)d_out;

    static cudaStream_t s_side = nullptr;
    static cudaEvent_t e_fork = nullptr, e_join = nullptr;
    static bool attr_set = false;
    if (!attr_set) {
        cudaFuncSetAttribute(k_proj2, cudaFuncAttributeMaxDynamicSharedMemorySize, PSM_TOT);
        cudaFuncSetAttribute(k_attnv8, cudaFuncAttributeMaxDynamicSharedMemorySize, AV8_SMEM);
        cudaStreamCreateWithFlags(&s_side, cudaStreamNonBlocking);
        cudaEventCreateWithFlags(&e_fork, cudaEventDisableTiming);
        cudaEventCreateWithFlags(&e_join, cudaEventDisableTiming);
        attr_set = true;
    }

    // fork: side stream runs wmat + x->fp16 conversion concurrently
    cudaEventRecord(e_fork, 0);
    cudaStreamWaitEvent(s_side, e_fork, 0);
    k_wmat<<<256, 256, 0, s_side>>>(vb_w, v_w);
    k_xhalf<<<1184, 256, 0, s_side>>>((const float4*)x1, 0, 4194304);
    k_xhalf<<<1184, 256, 0, s_side>>>((const float4*)x2, 1, 2359296);
    cudaEventRecord(e_join, s_side);

    // main chain
    k_embed8<<<200, 512>>>(x1, c1, x2, c2, fqk_w, fqk_b, fqk_g, cqk_w, cqk_b, cqk_g);
    k_attn3<<<dim3(7, 32), 512>>>();

    cudaStreamWaitEvent(0, e_join, 0);
    k_attnv8<<<dim3(8, 7, 32), 256, AV8_SMEM>>>();
    k_proj2<<<dim3(2, 148), 256, PSM_TOT>>>(out);
}

// round 17
// speedup vs baseline: 1.6915x; 1.3945x over previous
#include <cuda_runtime.h>
#include <cuda_bf16.h>
#include <cuda_fp16.h>
#include <cstdint>
#include <math.h>

// ---- problem constants ----
#define B_    4
#define NTOT  400
#define N1    256
#define N2    144
#define DIM   256
#define NH    8

// ---- scratch ----
__device__ float g_fqk[B_ * NTOT * 512];
__device__ float g_cqk[B_ * NTOT * 128];
__device__ __half g_attnf[B_ * NH * NTOT * 256];  // attn fp16 (cols>=cnt stay 0)
__device__ __half g_x1f[16777216];                // x1 fp16
__device__ __half g_x2f[9437184];                 // x2 fp16
__device__ __half g_mixf[26214400];               // attn-mixed x, fp16
__device__ __half g_w2f[65536];                   // W2 = vb_w @ v_w, fp16

// ============================================================================
// helpers
// ============================================================================
__device__ __forceinline__ uint32_t smem_u32(const void* p) {
    uint32_t a;
    asm("{ .reg .u64 t; cvta.to.shared.u64 t, %1; cvt.u32.u64 %0, t; }" : "=r"(a) : "l"(p));
    return a;
}

#define LDSM_X4(r0, r1, r2, r3, addr) \
    asm volatile("ldmatrix.sync.aligned.m8n8.x4.shared.b16 {%0,%1,%2,%3}, [%4];" \
        : "=r"(r0), "=r"(r1), "=r"(r2), "=r"(r3) : "r"(addr))

#define LDSM_X4_T(r0, r1, r2, r3, addr) \
    asm volatile("ldmatrix.sync.aligned.m8n8.x4.trans.shared.b16 {%0,%1,%2,%3}, [%4];" \
        : "=r"(r0), "=r"(r1), "=r"(r2), "=r"(r3) : "r"(addr))

// fp16 MMA
#define MMA16816F(d, a0, a1, a2, a3, b0, b1) \
    asm volatile("mma.sync.aligned.m16n8k16.row.col.f32.f16.f16.f32 " \
        "{%0,%1,%2,%3}, {%4,%5,%6,%7}, {%8,%9}, {%0,%1,%2,%3};" \
        : "+f"((d)[0]), "+f"((d)[1]), "+f"((d)[2]), "+f"((d)[3]) \
        : "r"(a0), "r"(a1), "r"(a2), "r"(a3), "r"(b0), "r"(b1))

#define CP16(dst, src) \
    asm volatile("cp.async.cg.shared.global [%0], [%1], 16;" :: "r"(dst), "l"(src))
#define CP_COMMIT() asm volatile("cp.async.commit_group;" ::: "memory")
#define CP_WAIT1()  asm volatile("cp.async.wait_group 1;" ::: "memory")
#define CP_WAIT0()  asm volatile("cp.async.wait_group 0;" ::: "memory")

__device__ __forceinline__ float* out_pixel_ptr(float* __restrict__ out, int m) {
    int b = m / 25600;
    int r = m % 25600;
    int w = r >> 6;
    int p = r & 63;
    int py = p >> 3, px = p & 7;
    if (w < N1) {
        int y = (w >> 4) * 8 + py, xx = (w & 15) * 8 + px;
        return out + ((size_t)((b * 128 + y) * 128 + xx)) * DIM;
    } else {
        int w2 = w - N1;
        int y = (w2 / 12) * 8 + py, xx = (w2 % 12) * 8 + px;
        return out + 16777216 + ((size_t)((b * 96 + y) * 96 + xx)) * DIM;
    }
}

// ============================================================================
// K0: convert x to fp16 (sel 0 -> g_x1f, 1 -> g_x2f).  Side-stream.
// ============================================================================
__global__ __launch_bounds__(256) void k_xhalf(const float4* __restrict__ src, int sel, int n4)
{
    __half2* d = (sel == 0) ? (__half2*)g_x1f : (__half2*)g_x2f;
    for (int i = blockIdx.x * 256 + threadIdx.x; i < n4; i += gridDim.x * 256) {
        float4 v = src[i];
        d[i * 2 + 0] = __floats2half2_rn(v.x, v.y);
        d[i * 2 + 1] = __floats2half2_rn(v.z, v.w);
    }
}

// ============================================================================
// K1 (R14-measured): window means -> QK proj -> RMS.  8 windows/block, grid 200.
// ============================================================================
__global__ __launch_bounds__(512) void k_embed8(
    const float* __restrict__ x1, const float* __restrict__ c1,
    const float* __restrict__ x2, const float* __restrict__ c2,
    const float* __restrict__ fqk_w, const float* __restrict__ fqk_b, const float* __restrict__ fqk_g,
    const float* __restrict__ cqk_w, const float* __restrict__ cqk_b, const float* __restrict__ cqk_g)
{
    int bw = blockIdx.x;
    int b = bw / 50, wg = (bw % 50) * 8;
    __shared__ __align__(16) float favg[8][256];
    __shared__ float cavg[8][4];
    __shared__ float redf[8][16];
    __shared__ float redc[8][4];
    int t = threadIdx.x;

    {
        int q = t >> 6, c = t & 63;
        int w = wg + q;
        const float* xbase;
        int rowstride;
        if (w < N1) {
            int wy = w >> 4, wx = w & 15;
            xbase = x1 + ((size_t)((b * 128 + wy * 8) * 128 + wx * 8)) * DIM;
            rowstride = 128 * DIM;
        } else {
            int w2 = w - N1;
            int wy = w2 / 12, wx = w2 % 12;
            xbase = x2 + ((size_t)((b * 96 + wy * 8) * 96 + wx * 8)) * DIM;
            rowstride = 96 * DIM;
        }
        const float* base = xbase + c * 4;
        float4 s = make_float4(0.f, 0.f, 0.f, 0.f);
        #pragma unroll
        for (int py = 0; py < 8; ++py)
            #pragma unroll
            for (int px = 0; px < 8; ++px) {
                float4 v = *(const float4*)(base + py * rowstride + px * DIM);
                s.x += v.x; s.y += v.y; s.z += v.z; s.w += v.w;
            }
        s.x *= (1.f / 64.f); s.y *= (1.f / 64.f); s.z *= (1.f / 64.f); s.w *= (1.f / 64.f);
        *(float4*)&favg[q][c * 4] = s;
    }
    if (t < 32) {
        int q = t >> 2, ch = t & 3;
        int w = wg + q;
        const float* cbase;
        int crowstride;
        if (w < N1) {
            int wy = w >> 4, wx = w & 15;
            cbase = c1 + ((size_t)((b * 128 + wy * 8) * 128 + wx * 8)) * 4;
            crowstride = 128 * 4;
        } else {
            int w2 = w - N1;
            int wy = w2 / 12, wx = w2 % 12;
            cbase = c2 + ((size_t)((b * 96 + wy * 8) * 96 + wx * 8)) * 4;
            crowstride = 96 * 4;
        }
        float s = 0.f;
        #pragma unroll
        for (int py = 0; py < 8; ++py)
            #pragma unroll
            for (int px = 0; px < 8; ++px)
                s += cbase[py * crowstride + px * 4 + ch];
        cavg[q][ch] = s * (1.f / 64.f);
    }
    __syncthreads();

    const float4* fw = (const float4*)(fqk_w + (size_t)t * 256);
    float raw[8];
    float bias = fqk_b[t];
    #pragma unroll
    for (int q = 0; q < 8; ++q) raw[q] = bias;
    #pragma unroll 8
    for (int d4 = 0; d4 < 64; ++d4) {
        float4 wv = fw[d4];
        #pragma unroll
        for (int q = 0; q < 8; ++q) {
            float4 av = ((const float4*)favg[q])[d4];
            raw[q] += wv.x * av.x + wv.y * av.y + wv.z * av.z + wv.w * av.w;
        }
    }
    float rawc[8];
    if (t < 128) {
        float cb = cqk_b[t];
        float w0 = cqk_w[t * 4 + 0], w1 = cqk_w[t * 4 + 1];
        float w2 = cqk_w[t * 4 + 2], w3 = cqk_w[t * 4 + 3];
        #pragma unroll
        for (int q = 0; q < 8; ++q)
            rawc[q] = cb + cavg[q][0] * w0 + cavg[q][1] * w1 + cavg[q][2] * w2 + cavg[q][3] * w3;
    }

    #pragma unroll
    for (int q = 0; q < 8; ++q) {
        float sf = raw[q] * raw[q];
        #pragma unroll
        for (int o = 16; o; o >>= 1) sf += __shfl_xor_sync(~0u, sf, o);
        if ((t & 31) == 0) redf[q][t >> 5] = sf;
    }
    if (t < 128) {
        #pragma unroll
        for (int q = 0; q < 8; ++q) {
            float sc = rawc[q] * rawc[q];
            #pragma unroll
            for (int o = 16; o; o >>= 1) sc += __shfl_xor_sync(~0u, sc, o);
            if ((t & 31) == 0) redc[q][t >> 5] = sc;
        }
    }
    __syncthreads();

    float gain = fqk_g[t];
    #pragma unroll
    for (int q = 0; q < 8; ++q) {
        float msf = 0.f;
        #pragma unroll
        for (int i = 0; i < 16; ++i) msf += redf[q][i];
        float invf = rsqrtf(msf * (1.f / 512.f) + 1e-6f);
        g_fqk[((size_t)(b * NTOT + wg + q)) * 512 + t] = raw[q] * invf * gain;
    }
    if (t < 128) {
        float cg = cqk_g[t];
        #pragma unroll
        for (int q = 0; q < 8; ++q) {
            float msc = redc[q][0] + redc[q][1] + redc[q][2] + redc[q][3];
            float invc = rsqrtf(msc * (1.f / 128.f) + 1e-6f);
            g_cqk[((size_t)(b * NTOT + wg + q)) * 128 + t] = rawc[q] * invc * cg;
        }
    }
}

// ============================================================================
// K2: W2 = vb_w @ v_w  (256x256), fp16
// ============================================================================
__global__ __launch_bounds__(256) void k_wmat(const float* __restrict__ vb_w,
                                              const float* __restrict__ v_w)
{
    int i = blockIdx.x, d = threadIdx.x;
    __shared__ float vb[256];
    vb[d] = vb_w[i * 256 + d];
    __syncthreads();
    float acc = 0.f;
    #pragma unroll 8
    for (int o = 0; o < 256; ++o) acc += vb[o] * v_w[o * 256 + d];
    g_w2f[i * 256 + d] = __float2half_rn(acc);
}

// ============================================================================
// K3 v3 (R16-measured): scores + softmax, tiled.  Writes attn as fp16.
// grid (7, 32), 512 threads = 64 rows x 8 lanes.
// ============================================================================
__global__ __launch_bounds__(512) void k_attn3()
{
    int tt = blockIdx.x;
    int bh = blockIdx.y;
    int b = bh >> 3, h = bh & 7;
    int n0 = tt * 64;
    int seg1 = (n0 >= N1);
    int colstart = seg1 ? 0 : N1;
    int cnt = seg1 ? N1 : N2;

    __shared__ __align__(16) float ksm[256][44];
    int t = threadIdx.x;

    for (int i = t; i < cnt * 10; i += 512) {
        int c = i / 10, j = i - c * 10;
        int mg = colstart + c;
        float4 v;
        if (j < 8)
            v = *(const float4*)(g_fqk + ((size_t)(b * NTOT + mg)) * 512 + 256 + h * 32 + j * 4);
        else
            v = *(const float4*)(g_cqk + ((size_t)(b * NTOT + mg)) * 128 + 64 + h * 8 + (j - 8) * 4);
        *(float4*)&ksm[c][j * 4] = v;
    }

    int r  = t >> 3;
    int cg = t & 7;
    int n = n0 + r;
    int nsafe = (n < NTOT) ? n : (NTOT - 1);
    float q[40];
    {
        const float* qf = g_fqk + ((size_t)(b * NTOT + nsafe)) * 512 + h * 32;
        const float* qc = g_cqk + ((size_t)(b * NTOT + nsafe)) * 128 + h * 8;
        #pragma unroll
        for (int i = 0; i < 32; ++i) q[i] = qf[i];
        #pragma unroll
        for (int i = 0; i < 8; ++i) q[32 + i] = qc[i];
    }
    __syncthreads();

    size_t dstbase = ((size_t)(bh * NTOT + nsafe)) * 256;
    bool wvalid = (n < NTOT);

    if (seg1) {
        float sc[32];
        float mx = -1e30f;
        #pragma unroll
        for (int it = 0; it < 32; ++it) {
            const float* kp = ksm[cg + it * 8];
            float s = 0.f, s2 = 0.f;
            #pragma unroll
            for (int i = 0; i < 32; ++i) s += q[i] * kp[i];
            #pragma unroll
            for (int i = 0; i < 8; ++i) s2 += q[32 + i] * kp[32 + i];
            float v = s * 0.1767766952966369f + s2 * 0.3535533905932738f;
            sc[it] = v;
            mx = fmaxf(mx, v);
        }
        #pragma unroll
        for (int o = 1; o < 8; o <<= 1) mx = fmaxf(mx, __shfl_xor_sync(~0u, mx, o));
        float sum = 0.f;
        #pragma unroll
        for (int it = 0; it < 32; ++it) { sc[it] = __expf(sc[it] - mx); sum += sc[it]; }
        #pragma unroll
        for (int o = 1; o < 8; o <<= 1) sum += __shfl_xor_sync(~0u, sum, o);
        float inv = 1.f / sum;
        if (wvalid) {
            #pragma unroll
            for (int it = 0; it < 32; ++it)
                g_attnf[dstbase + cg + it * 8] = __float2half_rn(sc[it] * inv);
        }
    } else {
        float sc[18];
        float mx = -1e30f;
        #pragma unroll
        for (int it = 0; it < 18; ++it) {
            const float* kp = ksm[cg + it * 8];
            float s = 0.f, s2 = 0.f;
            #pragma unroll
            for (int i = 0; i < 32; ++i) s += q[i] * kp[i];
            #pragma unroll
            for (int i = 0; i < 8; ++i) s2 += q[32 + i] * kp[32 + i];
            float v = s * 0.1767766952966369f + s2 * 0.3535533905932738f;
            sc[it] = v;
            mx = fmaxf(mx, v);
        }
        #pragma unroll
        for (int o = 1; o < 8; o <<= 1) mx = fmaxf(mx, __shfl_xor_sync(~0u, mx, o));
        float sum = 0.f;
        #pragma unroll
        for (int it = 0; it < 18; ++it) { sc[it] = __expf(sc[it] - mx); sum += sc[it]; }
        #pragma unroll
        for (int o = 1; o < 8; o <<= 1) sum += __shfl_xor_sync(~0u, sum, o);
        float inv = 1.f / sum;
        if (wvalid) {
            #pragma unroll
            for (int it = 0; it < 18; ++it)
                g_attnf[dstbase + cg + it * 8] = __float2half_rn(sc[it] * inv);
        }
    }
}

// ============================================================================
// K4 v9: mix = attn @ X via single-product fp16 HMMA (R16-measured core).
// Epilogue now writes fp16 mix (single array).  grid (8, 7, 32), 256 thr.
// ============================================================================
#define AV8_SMEM (10240 + 2 * 16896)   // 44032

__global__ __launch_bounds__(256)
void k_attnv9()
{
    extern __shared__ __align__(128) char sm[];
    uint32_t sb = smem_u32(sm);
    int tid = threadIdx.x;
    int lane = tid & 31, wid = tid >> 5;
    int wm = wid >> 2, wn = wid & 3;

    int bh = blockIdx.z;
    int b = bh >> 3, h = bh & 7;
    int n0 = blockIdx.y * 64;
    int j0 = blockIdx.x * 256;
    int seg1 = (n0 >= N1);
    int kExt = seg1 ? N1 : N2;
    int nkc = (kExt + 31) >> 5;           // 8 or 5

    int pp = 8 * h + blockIdx.x;
    int py = pp >> 3, px = pp & 7;
    const __half* bsrc;
    int W;
    if (seg1) { bsrc = g_x1f + (size_t)b * 4194304; W = 128; }
    else      { bsrc = g_x2f + (size_t)b * 2359296; W = 96;  }

    int alrow = tid >> 2;
    int apart = (tid & 3) * 16;
    int aglob = n0 + alrow; if (aglob > NTOT - 1) aglob = NTOT - 1;
    const char* aSrc = (const char*)(g_attnf + ((size_t)bh * NTOT + aglob) * 256) + apart;
    uint32_t aDst = (uint32_t)(alrow * 80 + apart);

    int brow = tid >> 3;
    int bpart = (tid & 7) * 64;

    #define AV_ISSUE(st, kc) do { \
        uint32_t ad = sb + (st) * 5120 + aDst; \
        CP16(ad, aSrc + (kc) * 64); \
        int idx_ = (kc) * 32 + brow; if (idx_ > kExt - 1) idx_ = kExt - 1; \
        int wy_, wx_; \
        if (seg1) { wy_ = idx_ >> 4; wx_ = idx_ & 15; } \
        else      { wy_ = idx_ / 12; wx_ = idx_ - wy_ * 12; } \
        size_t off_ = ((size_t)((wy_ * 8 + py) * W + wx_ * 8 + px)) * 256; \
        const char* bs_ = (const char*)(bsrc + off_) + bpart; \
        uint32_t bd = sb + 10240 + (st) * 16896 + (uint32_t)(brow * 528 + bpart); \
        CP16(bd,      bs_);      CP16(bd + 16, bs_ + 16); \
        CP16(bd + 32, bs_ + 32); CP16(bd + 48, bs_ + 48); \
        CP_COMMIT(); \
    } while (0)

    AV_ISSUE(0, 0);
    AV_ISSUE(1, 1);

    float acc[2][8][4];
    #pragma unroll
    for (int mt = 0; mt < 2; ++mt)
        #pragma unroll
        for (int nt = 0; nt < 8; ++nt)
            #pragma unroll
            for (int q = 0; q < 4; ++q) acc[mt][nt][q] = 0.f;

    uint32_t lma_off = (uint32_t)((wm * 32 + (lane & 15)) * 80 + (lane >> 4) * 16);
    uint32_t lmb_off = (uint32_t)(((((lane >> 3) & 1) * 8 + (lane & 7)) * 528)
                                  + wn * 128 + (lane >> 4) * 16);

    for (int kc = 0; kc < nkc; ++kc) {
        if (kc == nkc - 1) { CP_WAIT0(); } else { CP_WAIT1(); }
        __syncthreads();
        int ksmax = (kExt - kc * 32 >= 32) ? 2 : 1;
        uint32_t aBase = sb + (uint32_t)((kc & 1) * 5120);
        uint32_t bBase = sb + 10240 + (uint32_t)((kc & 1) * 16896);
        for (int ks = 0; ks < ksmax; ++ks) {
            uint32_t ka = aBase + lma_off + ks * 32;
            uint32_t kb = bBase + lmb_off + ks * (16 * 528);
            uint32_t ah[2][4];
            LDSM_X4(ah[0][0], ah[0][1], ah[0][2], ah[0][3], ka);
            LDSM_X4(ah[1][0], ah[1][1], ah[1][2], ah[1][3], ka + 16 * 80);
            #pragma unroll
            for (int ng = 0; ng < 4; ++ng) {
                uint32_t bf[4];
                LDSM_X4_T(bf[0], bf[1], bf[2], bf[3], kb + ng * 32);
                #pragma unroll
                for (int hf = 0; hf < 2; ++hf) {
                    int nt = ng * 2 + hf;
                    uint32_t b0 = bf[hf * 2], b1 = bf[hf * 2 + 1];
                    #pragma unroll
                    for (int mt = 0; mt < 2; ++mt)
                        MMA16816F(acc[mt][nt], ah[mt][0], ah[mt][1], ah[mt][2], ah[mt][3], b0, b1);
                }
            }
        }
        __syncthreads();
        if (kc + 2 < nkc) AV_ISSUE(kc & 1, kc + 2);
    }
    #undef AV_ISSUE

    // epilogue -> fp16 mix
    #pragma unroll
    for (int mt = 0; mt < 2; ++mt) {
        #pragma unroll
        for (int hrow = 0; hrow < 2; ++hrow) {
            int n = n0 + wm * 32 + mt * 16 + (lane >> 2) + hrow * 8;
            if (n < NTOT) {
                size_t idx = ((size_t)(b * NTOT + n)) * 16384 + h * 2048 + j0
                           + wn * 64 + (lane & 3) * 2;
                #pragma unroll
                for (int nt = 0; nt < 8; ++nt) {
                    __half2 v = __floats2half2_rn(acc[mt][nt][hrow * 2 + 0],
                                                  acc[mt][nt][hrow * 2 + 1]);
                    *(__half2*)(g_mixf + idx + nt * 8) = v;
                }
            }
        }
    }
}

// ============================================================================
// K5 v3: out = mix @ W2^T via single-product fp16 HMMA — persistent W2 in smem.
// Grid (2, 296), 256 thr, 2 CTAs/SM, dyn smem 102400:
//   B: [kc:8][row:128][80B] @ 0      (81920)
//   A: 2 stages x 10240              @ 81920
// ============================================================================
#define P3_A   81920
#define P3_TOT 102400

__global__ __launch_bounds__(256, 2)
void k_proj3(float* __restrict__ Cout)
{
    extern __shared__ __align__(128) char sm[];
    uint32_t sb = smem_u32(sm);
    int tid = threadIdx.x;
    int lane = tid & 31, wid = tid >> 5;
    int wm = wid >> 1, wn = wid & 1;
    int n0 = blockIdx.x * 128;

    int lrow = tid >> 1;
    int half = tid & 1;
    uint32_t dbase = (uint32_t)(lrow * 80 + half * 32);

    // persistent W2 load (once per CTA)
    {
        const char* ph = (const char*)g_w2f + ((size_t)(n0 + lrow) * 256 + half * 16) * 2;
        #pragma unroll
        for (int kc = 0; kc < 8; ++kc) {
            uint32_t d = sb + kc * 10240 + dbase;
            CP16(d,      ph + kc * 64);
            CP16(d + 16, ph + kc * 64 + 16);
        }
        CP_COMMIT();
    }

    uint32_t lma_off = (uint32_t)(P3_A + (wm * 32 + (lane & 15)) * 80 + (lane >> 4) * 16);
    uint32_t lmb_off = (uint32_t)((wn * 64 + (lane & 7) + ((lane >> 4) & 1) * 8) * 80
                                  + ((lane >> 3) & 1) * 16);

    for (int mt = blockIdx.y; mt < 800; mt += (int)gridDim.y) {
        int m0 = mt * 128;
        const char* pA = (const char*)g_mixf + ((size_t)(m0 + lrow) * 256 + half * 16) * 2;

        #define AISSUE(st, kc) do { \
            uint32_t d0 = sb + P3_A + (st) * 10240 + dbase; \
            CP16(d0,      pA + (kc) * 64); \
            CP16(d0 + 16, pA + (kc) * 64 + 16); \
            CP_COMMIT(); \
        } while (0)

        AISSUE(0, 0);
        AISSUE(1, 1);

        float acc[2][8][4];
        #pragma unroll
        for (int mtt = 0; mtt < 2; ++mtt)
            #pragma unroll
            for (int nt = 0; nt < 8; ++nt)
                #pragma unroll
                for (int q = 0; q < 4; ++q) acc[mtt][nt][q] = 0.f;

        for (int kc = 0; kc < 8; ++kc) {
            if (kc == 7) { CP_WAIT0(); } else { CP_WAIT1(); }
            __syncthreads();
            uint32_t lm_a = sb + (uint32_t)((kc & 1) * 10240) + lma_off;
            uint32_t lm_b = sb + (uint32_t)(kc * 10240) + lmb_off;
            #pragma unroll
            for (int ks = 0; ks < 2; ++ks) {
                uint32_t ka = lm_a + ks * 32;
                uint32_t kb = lm_b + ks * 32;
                uint32_t ah[2][4];
                LDSM_X4(ah[0][0], ah[0][1], ah[0][2], ah[0][3], ka);
                LDSM_X4(ah[1][0], ah[1][1], ah[1][2], ah[1][3], ka + 16 * 80);
                #pragma unroll
                for (int ng = 0; ng < 4; ++ng) {
                    uint32_t bf[4];
                    LDSM_X4(bf[0], bf[1], bf[2], bf[3], kb + ng * (16 * 80));
                    #pragma unroll
                    for (int hf = 0; hf < 2; ++hf) {
                        int nt = ng * 2 + hf;
                        uint32_t b0 = bf[hf * 2], b1 = bf[hf * 2 + 1];
                        #pragma unroll
                        for (int mtt = 0; mtt < 2; ++mtt)
                            MMA16816F(acc[mtt][nt], ah[mtt][0], ah[mtt][1], ah[mtt][2], ah[mtt][3], b0, b1);
                    }
                }
            }
            __syncthreads();
            if (kc + 2 < 8) AISSUE(kc & 1, kc + 2);
        }
        #undef AISSUE

        #pragma unroll
        for (int mtt = 0; mtt < 2; ++mtt) {
            #pragma unroll
            for (int hrow = 0; hrow < 2; ++hrow) {
                int m = m0 + wm * 32 + mtt * 16 + (lane >> 2) + hrow * 8;
                float* dst = out_pixel_ptr(Cout, m) + n0 + wn * 64 + (lane & 3) * 2;
                #pragma unroll
                for (int nt = 0; nt < 8; ++nt) {
                    float2 v = make_float2(acc[mtt][nt][hrow * 2 + 0], acc[mtt][nt][hrow * 2 + 1]);
                    *(float2*)(dst + nt * 8) = v;
                }
            }
        }
    }
}

// ============================================================================
extern "C" void kernel_launch(void* const* d_in, const int* in_sizes, int n_in,
                              void* d_out, int out_size)
{
    const float* x1    = (const float*)d_in[0];
    const float* c1    = (const float*)d_in[1];
    const float* x2    = (const float*)d_in[2];
    const float* c2    = (const float*)d_in[3];
    const float* fqk_w = (const float*)d_in[4];
    const float* fqk_b = (const float*)d_in[5];
    const float* fqk_g = (const float*)d_in[6];
    const float* cqk_w = (const float*)d_in[7];
    const float* cqk_b = (const float*)d_in[8];
    const float* cqk_g = (const float*)d_in[9];
    const float* v_w   = (const float*)d_in[10];
    const float* vb_w  = (const float*)d_in[11];
    float* out = (float*)d_out;

    static cudaStream_t s_side = nullptr;
    static cudaEvent_t e_fork = nullptr, e_join = nullptr;
    static bool attr_set = false;
    if (!attr_set) {
        cudaFuncSetAttribute(k_proj3, cudaFuncAttributeMaxDynamicSharedMemorySize, P3_TOT);
        cudaFuncSetAttribute(k_attnv9, cudaFuncAttributeMaxDynamicSharedMemorySize, AV8_SMEM);
        cudaStreamCreateWithFlags(&s_side, cudaStreamNonBlocking);
        cudaEventCreateWithFlags(&e_fork, cudaEventDisableTiming);
        cudaEventCreateWithFlags(&e_join, cudaEventDisableTiming);
        attr_set = true;
    }

    // fork: side stream runs wmat + x->fp16 conversion concurrently
    cudaEventRecord(e_fork, 0);
    cudaStreamWaitEvent(s_side, e_fork, 0);
    k_wmat<<<256, 256, 0, s_side>>>(vb_w, v_w);
    k_xhalf<<<1184, 256, 0, s_side>>>((const float4*)x1, 0, 4194304);
    k_xhalf<<<1184, 256, 0, s_side>>>((const float4*)x2, 1, 2359296);
    cudaEventRecord(e_join, s_side);

    // main chain
    k_embed8<<<200, 512>>>(x1, c1, x2, c2, fqk_w, fqk_b, fqk_g, cqk_w, cqk_b, cqk_g);
    k_attn3<<<dim3(7, 32), 512>>>();

    cudaStreamWaitEvent(0, e_join, 0);
    k_attnv9<<<dim3(8, 7, 32), 256, AV8_SMEM>>>();
    k_proj3<<<dim3(2, 296), 256, P3_TOT>>>(out);
}